// round 16
// baseline (speedup 1.0000x reference)
#include <cuda_runtime.h>
#include <cuda_fp16.h>
#include <cstdint>

// Fixed shapes
#define BATCH 2
#define HEADS 16
#define SEQ   2048
#define DK    64
#define BH    (BATCH*HEADS)

#define TQ 64            // query rows per CTA
#define TK 64            // keys per tile
#define NT (SEQ/TK)      // 32 tiles

// smem byte offsets (dynamic buffer)
#define QB    0          // Q 64x64 half (9216)
#define KB0   9216       // K buf0 (9216)
#define KB1   18432      // K buf1 (9216)
#define VB0   27648      // V buf0 (9216)
#define VB1   36864      // V buf1 (9216)
#define ADDB  46080      // addend float[2048] (8192)
#define LB    54272      // L partials float[4][64] (1024)
#define ILB   55296      // invL float[64] (256)
#define SMEM_BYTES 55552

#define E16F   8886110.5f      // e^16
#define INVE16 1.1253517e-7f   // e^-16

// fp16 K/V scratch (16 MB static)
__device__ __half g_K16[(size_t)BH * SEQ * DK];
__device__ __half g_V16[(size_t)BH * SEQ * DK];

__device__ __forceinline__ uint32_t pack2(float lo, float hi) {
    __half2 h = __floats2half2_rn(lo, hi);
    return *reinterpret_cast<uint32_t*>(&h);
}
__device__ __forceinline__ uint2 f4h(float4 v) {
    return make_uint2(pack2(v.x, v.y), pack2(v.z, v.w));
}
__device__ __forceinline__ void mma16(float c[4],
                                      uint32_t a0, uint32_t a1, uint32_t a2, uint32_t a3,
                                      uint32_t b0, uint32_t b1) {
    asm volatile(
        "mma.sync.aligned.m16n8k16.row.col.f32.f16.f16.f32 "
        "{%0,%1,%2,%3}, {%4,%5,%6,%7}, {%8,%9}, {%0,%1,%2,%3};\n"
        : "+f"(c[0]), "+f"(c[1]), "+f"(c[2]), "+f"(c[3])
        : "r"(a0), "r"(a1), "r"(a2), "r"(a3), "r"(b0), "r"(b1));
}
__device__ __forceinline__ void ldsm4(uint32_t& r0, uint32_t& r1, uint32_t& r2, uint32_t& r3,
                                      uint32_t a) {
    asm volatile("ldmatrix.sync.aligned.m8n8.x4.shared.b16 {%0,%1,%2,%3}, [%4];"
                 : "=r"(r0), "=r"(r1), "=r"(r2), "=r"(r3) : "r"(a));
}
__device__ __forceinline__ void ldsm4t(uint32_t& r0, uint32_t& r1, uint32_t& r2, uint32_t& r3,
                                       uint32_t a) {
    asm volatile("ldmatrix.sync.aligned.m8n8.x4.trans.shared.b16 {%0,%1,%2,%3}, [%4];"
                 : "=r"(r0), "=r"(r1), "=r"(r2), "=r"(r3) : "r"(a));
}
#define CP16(dst, src) \
    asm volatile("cp.async.cg.shared.global [%0], [%1], 16;" :: "r"(dst), "l"(src) : "memory")
#define CP_COMMIT() asm volatile("cp.async.commit_group;" ::: "memory")
#define CP_WAIT1()  asm volatile("cp.async.wait_group 1;" ::: "memory")

// ---------------- prep: K,V -> fp16 ----------------
__global__ __launch_bounds__(256)
void cvt_kernel(const float* __restrict__ K, const float* __restrict__ V)
{
    size_t i = (size_t)blockIdx.x * 256 + threadIdx.x;   // BH*SEQ*DK/4 = 1M float4
    reinterpret_cast<uint2*>(g_K16)[i] = f4h(reinterpret_cast<const float4*>(K)[i]);
    reinterpret_cast<uint2*>(g_V16)[i] = f4h(reinterpret_cast<const float4*>(V)[i]);
}

// ---------------- main attention ----------------
__global__ __launch_bounds__(256, 2)
void attn_h16_kernel(const float* __restrict__ Q,
                     const int*   __restrict__ mask,
                     float* __restrict__ out,     // may be null
                     float* __restrict__ wout)    // may be null (normalized)
{
    extern __shared__ __align__(16) char smc[];
    float* sadd = reinterpret_cast<float*>(smc + ADDB);
    float* sL   = reinterpret_cast<float*>(smc + LB);
    float* sIL  = reinterpret_cast<float*>(smc + ILB);

    const int tid  = threadIdx.x;
    const int lane = tid & 31;
    const int warp = tid >> 5;
    const int g    = lane >> 2;          // 0..7
    const int tg   = lane & 3;           // 0..3
    const int mw2  = warp >> 2;          // 0..1  (m32 block)
    const int nw4  = warp & 3;           // 0..3  (n16/k16 block)

    const int bh = blockIdx.y;
    const int q0 = blockIdx.x * TQ;
    const int b  = bh >> 4;

    const uint32_t smb = (uint32_t)__cvta_generic_to_shared(smc);

    // ---- Q tile (scaled fp16) + mask addend (-16 shift folded) ----
    {
        const float4* Qg = reinterpret_cast<const float4*>(
            Q + ((size_t)bh * SEQ + q0) * DK);
        #pragma unroll
        for (int i = 0; i < 4; ++i) {
            int fi = i * 256 + tid, row = fi >> 4, c4 = fi & 15;
            float4 v = Qg[fi];
            v.x *= 0.125f; v.y *= 0.125f; v.z *= 0.125f; v.w *= 0.125f;
            *reinterpret_cast<uint2*>(smc + QB + row * 144 + c4 * 8) = f4h(v);
        }
        const int* mrow = mask + (size_t)b * SEQ;
        #pragma unroll
        for (int i = 0; i < 8; ++i) {
            int k = i * 256 + tid;
            sadd[k] = mrow[k] ? -16.0f : -1e9f;
        }
    }
    __syncthreads();

    // ---- ldmatrix lane addressing ----
    const int laneRow = (lane & 7) + ((lane >> 3) & 1) * 8;
    const int laneSel = (lane >> 4) & 1;
    const uint32_t rowOff = (uint32_t)((nw4 * 16 + laneRow) * 144 + laneSel * 16);

    // ---- Q A-frags for 2 m16 tiles (shared by both passes) ----
    uint32_t qa[2][4][4];
    #pragma unroll
    for (int i = 0; i < 2; ++i) {
        uint32_t a = smb + QB + (uint32_t)((mw2 * 32 + i * 16 + laneRow) * 144 + laneSel * 16);
        #pragma unroll
        for (int kc = 0; kc < 4; ++kc)
            ldsm4(qa[i][kc][0], qa[i][kc][1], qa[i][kc][2], qa[i][kc][3], a + kc * 32);
    }

    const uint4* K16g = reinterpret_cast<const uint4*>(g_K16 + (size_t)bh * SEQ * DK);
    const uint4* V16g = reinterpret_cast<const uint4*>(g_V16 + (size_t)bh * SEQ * DK);

    // =============== PASS 1: L only (m32 x n16; KB0/KB1 ping-pong) ===============
    {
        float lg[2][2] = {};   // [m-tile][row-half]

        uint4 kf[2];
        #pragma unroll
        for (int i = 0; i < 2; ++i) kf[i] = K16g[i * 256 + tid];
        #pragma unroll
        for (int i = 0; i < 2; ++i) {
            int fi = i * 256 + tid;
            *reinterpret_cast<uint4*>(smc + KB0 + (fi >> 3) * 144 + (fi & 7) * 16) = kf[i];
        }
        __syncthreads();
        #pragma unroll
        for (int i = 0; i < 2; ++i) kf[i] = K16g[512 + i * 256 + tid];

        for (int t = 0; t < NT; ++t) {
            const uint32_t curB = (t & 1) ? KB1 : KB0;
            if (t + 1 < NT) {
                const uint32_t nxtB = ((t + 1) & 1) ? KB1 : KB0;
                #pragma unroll
                for (int i = 0; i < 2; ++i) {
                    int fi = i * 256 + tid;
                    *reinterpret_cast<uint4*>(smc + nxtB + (fi >> 3) * 144 + (fi & 7) * 16) = kf[i];
                }
            }
            if (t + 2 < NT) {
                #pragma unroll
                for (int i = 0; i < 2; ++i)
                    kf[i] = K16g[(size_t)(t + 2) * 512 + i * 256 + tid];
            }

            float acc[2][2][4] = {};
            #pragma unroll
            for (int kc = 0; kc < 4; ++kc) {
                uint32_t r0, r1, r2, r3;
                ldsm4(r0, r1, r2, r3, smb + curB + rowOff + kc * 32);
                #pragma unroll
                for (int i = 0; i < 2; ++i) {
                    mma16(acc[i][0], qa[i][kc][0], qa[i][kc][1], qa[i][kc][2], qa[i][kc][3], r0, r2);
                    mma16(acc[i][1], qa[i][kc][0], qa[i][kc][1], qa[i][kc][2], qa[i][kc][3], r1, r3);
                }
            }
            #pragma unroll
            for (int i = 0; i < 2; ++i) {
                #pragma unroll
                for (int p = 0; p < 2; ++p) {
                    int colL = nw4 * 16 + p * 8 + 2 * tg;
                    float2 ad = *reinterpret_cast<const float2*>(sadd + t * TK + colL);
                    lg[i][0] += __expf(acc[i][p][0] + ad.x) + __expf(acc[i][p][1] + ad.y);
                    lg[i][1] += __expf(acc[i][p][2] + ad.x) + __expf(acc[i][p][3] + ad.y);
                }
            }
            __syncthreads();
        }

        #pragma unroll
        for (int i = 0; i < 2; ++i)
            #pragma unroll
            for (int h = 0; h < 2; ++h) {
                lg[i][h] += __shfl_xor_sync(~0u, lg[i][h], 1);
                lg[i][h] += __shfl_xor_sync(~0u, lg[i][h], 2);
            }
        if (tg == 0) {
            #pragma unroll
            for (int i = 0; i < 2; ++i) {
                sL[nw4 * TQ + mw2 * 32 + i * 16 + g]     = lg[i][0];
                sL[nw4 * TQ + mw2 * 32 + i * 16 + g + 8] = lg[i][1];
            }
        }
        __syncthreads();
        if (tid < TQ)
            sIL[tid] = 1.0f / (sL[tid] + sL[TQ + tid] + sL[2 * TQ + tid] + sL[3 * TQ + tid]);
        __syncthreads();
    }

    const float inv00 = sIL[mw2 * 32 + g];
    const float inv08 = sIL[mw2 * 32 + g + 8];
    const float inv10 = sIL[mw2 * 32 + 16 + g];
    const float inv18 = sIL[mw2 * 32 + 16 + g + 8];

    // =============== PASS 2: m32 x k16, cp.async K/V, W + PV ===============
    float o[2][8][4] = {};
    {
        // async issue of tile t into parity buffers (4 x 16B per thread)
        auto issue = [&](int t) {
            const uint32_t kb = smb + ((t & 1) ? KB1 : KB0);
            const uint32_t vb = smb + ((t & 1) ? VB1 : VB0);
            #pragma unroll
            for (int i = 0; i < 2; ++i) {
                int fi = i * 256 + tid;
                uint32_t d = (uint32_t)((fi >> 3) * 144 + (fi & 7) * 16);
                CP16(kb + d, (const void*)(K16g + (size_t)t * 512 + fi));
                CP16(vb + d, (const void*)(V16g + (size_t)t * 512 + fi));
            }
            CP_COMMIT();
        };
        issue(0);
        issue(1);

        for (int t = 0; t < NT; ++t) {
            CP_WAIT1();
            __syncthreads();   // tile t resident for all threads; prior reads of this buffer done

            // --- QK: 4 ldsm.x4, 8 mma (B-frags shared across 2 m-tiles) ---
            const uint32_t kb = smb + ((t & 1) ? KB1 : KB0) + rowOff;
            float acc[2][2][4] = {};
            #pragma unroll
            for (int kc = 0; kc < 4; ++kc) {
                uint32_t r0, r1, r2, r3;
                ldsm4(r0, r1, r2, r3, kb + kc * 32);
                #pragma unroll
                for (int i = 0; i < 2; ++i) {
                    mma16(acc[i][0], qa[i][kc][0], qa[i][kc][1], qa[i][kc][2], qa[i][kc][3], r0, r2);
                    mma16(acc[i][1], qa[i][kc][0], qa[i][kc][1], qa[i][kc][2], qa[i][kc][3], r1, r3);
                }
            }

            // --- u = exp(s+ad); write normalized W; build fp16 P frags ---
            uint32_t pa[2][4];
            #pragma unroll
            for (int i = 0; i < 2; ++i) {
                const float iv0 = i ? inv10 : inv00;
                const float iv8 = i ? inv18 : inv08;
                #pragma unroll
                for (int p = 0; p < 2; ++p) {
                    int colL = nw4 * 16 + p * 8 + 2 * tg;
                    float2 ad = *reinterpret_cast<const float2*>(sadd + t * TK + colL);
                    float u00 = __expf(acc[i][p][0] + ad.x);
                    float u01 = __expf(acc[i][p][1] + ad.y);
                    float u10 = __expf(acc[i][p][2] + ad.x);
                    float u11 = __expf(acc[i][p][3] + ad.y);
                    if (wout) {
                        size_t wb = ((size_t)bh * SEQ + q0 + mw2 * 32 + i * 16 + g) * SEQ
                                  + t * TK + colL;
                        *reinterpret_cast<float2*>(wout + wb)           = make_float2(u00 * iv0, u01 * iv0);
                        *reinterpret_cast<float2*>(wout + wb + 8 * SEQ) = make_float2(u10 * iv8, u11 * iv8);
                    }
                    pa[i][2*p]     = pack2(u00 * E16F, u01 * E16F);
                    pa[i][2*p + 1] = pack2(u10 * E16F, u11 * E16F);
                }
            }

            // --- PV: 4 ldsm.x4.trans, 16 mma (V-frags shared across 2 m-tiles) ---
            const uint32_t vb = smb + ((t & 1) ? VB1 : VB0) + rowOff;
            #pragma unroll
            for (int dp = 0; dp < 4; ++dp) {
                uint32_t r0, r1, r2, r3;
                ldsm4t(r0, r1, r2, r3, vb + dp * 32);
                #pragma unroll
                for (int i = 0; i < 2; ++i) {
                    mma16(o[i][2*dp],     pa[i][0], pa[i][1], pa[i][2], pa[i][3], r0, r1);
                    mma16(o[i][2*dp + 1], pa[i][0], pa[i][1], pa[i][2], pa[i][3], r2, r3);
                }
            }
            __syncthreads();   // all reads of buffer (t&1) done before re-fill
            if (t + 2 < NT) issue(t + 2);
        }
    }

    // =============== epilogue: 4-way O reduce across nw4, write out ===============
    __syncthreads();
    float* red = reinterpret_cast<float*>(smc);   // 2 regions x 64x68 fp32 = 34816 B
    const int row0 = mw2 * 32 + g;

    if (nw4 >= 2) {
        float* rg = red + (nw4 - 2) * (64 * 68);
        #pragma unroll
        for (int i = 0; i < 2; ++i)
            #pragma unroll
            for (int dn = 0; dn < 8; ++dn) {
                int r = row0 + i * 16, c = dn * 8 + 2 * tg;
                rg[r * 68 + c]           = o[i][dn][0];
                rg[r * 68 + c + 1]       = o[i][dn][1];
                rg[(r + 8) * 68 + c]     = o[i][dn][2];
                rg[(r + 8) * 68 + c + 1] = o[i][dn][3];
            }
    }
    __syncthreads();
    if (nw4 < 2) {
        float* rg = red + nw4 * (64 * 68);
        #pragma unroll
        for (int i = 0; i < 2; ++i)
            #pragma unroll
            for (int dn = 0; dn < 8; ++dn) {
                int r = row0 + i * 16, c = dn * 8 + 2 * tg;
                o[i][dn][0] += rg[r * 68 + c];
                o[i][dn][1] += rg[r * 68 + c + 1];
                o[i][dn][2] += rg[(r + 8) * 68 + c];
                o[i][dn][3] += rg[(r + 8) * 68 + c + 1];
            }
    }
    __syncthreads();
    if (nw4 == 1) {
        float* rg = red;
        #pragma unroll
        for (int i = 0; i < 2; ++i)
            #pragma unroll
            for (int dn = 0; dn < 8; ++dn) {
                int r = row0 + i * 16, c = dn * 8 + 2 * tg;
                rg[r * 68 + c]           = o[i][dn][0];
                rg[r * 68 + c + 1]       = o[i][dn][1];
                rg[(r + 8) * 68 + c]     = o[i][dn][2];
                rg[(r + 8) * 68 + c + 1] = o[i][dn][3];
            }
    }
    __syncthreads();
    if (nw4 == 0 && out) {
        #pragma unroll
        for (int i = 0; i < 2; ++i) {
            const float s0 = (i ? inv10 : inv00) * INVE16;
            const float s8 = (i ? inv18 : inv08) * INVE16;
            int r = row0 + i * 16;
            size_t base = ((size_t)bh * SEQ + q0 + r) * DK;
            #pragma unroll
            for (int dn = 0; dn < 8; ++dn) {
                int c = dn * 8 + 2 * tg;
                float2 lo = make_float2((o[i][dn][0] + red[r * 68 + c])           * s0,
                                        (o[i][dn][1] + red[r * 68 + c + 1])       * s0);
                float2 hi = make_float2((o[i][dn][2] + red[(r + 8) * 68 + c])     * s8,
                                        (o[i][dn][3] + red[(r + 8) * 68 + c + 1]) * s8);
                *reinterpret_cast<float2*>(out + base + c)          = lo;
                *reinterpret_cast<float2*>(out + base + 8 * DK + c) = hi;
            }
        }
    }
}

extern "C" void kernel_launch(void* const* d_in, const int* in_sizes, int n_in,
                              void* d_out, int out_size)
{
    const float* Q    = (const float*)d_in[0];
    const float* K    = (const float*)d_in[1];
    const float* V    = (const float*)d_in[2];
    const int*   mask = (const int*)d_in[3];

    const long long O = (long long)BH * SEQ * DK;    //   4,194,304
    const long long W = (long long)BH * SEQ * SEQ;   // 134,217,728

    float* out_ptr = nullptr;
    float* w_ptr   = nullptr;
    if ((long long)out_size >= O + W) {
        out_ptr = (float*)d_out;
        w_ptr   = (float*)d_out + O;
    } else if ((long long)out_size == W) {
        w_ptr   = (float*)d_out;
    } else {
        out_ptr = (float*)d_out;
    }

    cvt_kernel<<<4096, 256>>>(K, V);

    cudaFuncSetAttribute(attn_h16_kernel,
                         cudaFuncAttributeMaxDynamicSharedMemorySize, SMEM_BYTES);
    dim3 grid(SEQ / TQ, BH);
    attn_h16_kernel<<<grid, 256, SMEM_BYTES>>>(Q, mask, out_ptr, w_ptr);
}

// round 17
// speedup vs baseline: 1.1625x; 1.1625x over previous
#include <cuda_runtime.h>
#include <cuda_fp16.h>
#include <cstdint>

// Fixed shapes
#define BATCH 2
#define HEADS 16
#define SEQ   2048
#define DK    64
#define BH    (BATCH*HEADS)

#define TQ 64            // query rows per CTA
#define TK 64            // keys per tile
#define NT (SEQ/TK)      // 32 tiles

// smem byte offsets (dynamic buffer). Buf(j) = 9216 + j*9216, j=0..3
#define QB    0          // Q 64x64 half (9216)
#define BUF0  9216       // pass1: K ring 0..3 ; pass2: KB0,KB1,VB0,VB1
#define ADDB  46080      // addend float[2048] (8192)
#define LB    54272      // L partials float[8][64] (2048)
#define ILB   56320      // invL float[64] (256)
#define SMEM_BYTES 56576

#define E16F   8886110.5f      // e^16
#define INVE16 1.1253517e-7f   // e^-16

// fp16 K/V scratch (16 MB static)
__device__ __half g_K16[(size_t)BH * SEQ * DK];
__device__ __half g_V16[(size_t)BH * SEQ * DK];

__device__ __forceinline__ uint32_t pack2(float lo, float hi) {
    __half2 h = __floats2half2_rn(lo, hi);
    return *reinterpret_cast<uint32_t*>(&h);
}
__device__ __forceinline__ uint2 f4h(float4 v) {
    return make_uint2(pack2(v.x, v.y), pack2(v.z, v.w));
}
__device__ __forceinline__ void mma16(float c[4],
                                      uint32_t a0, uint32_t a1, uint32_t a2, uint32_t a3,
                                      uint32_t b0, uint32_t b1) {
    asm volatile(
        "mma.sync.aligned.m16n8k16.row.col.f32.f16.f16.f32 "
        "{%0,%1,%2,%3}, {%4,%5,%6,%7}, {%8,%9}, {%0,%1,%2,%3};\n"
        : "+f"(c[0]), "+f"(c[1]), "+f"(c[2]), "+f"(c[3])
        : "r"(a0), "r"(a1), "r"(a2), "r"(a3), "r"(b0), "r"(b1));
}
__device__ __forceinline__ void ldsm4(uint32_t& r0, uint32_t& r1, uint32_t& r2, uint32_t& r3,
                                      uint32_t a) {
    asm volatile("ldmatrix.sync.aligned.m8n8.x4.shared.b16 {%0,%1,%2,%3}, [%4];"
                 : "=r"(r0), "=r"(r1), "=r"(r2), "=r"(r3) : "r"(a));
}
__device__ __forceinline__ void ldsm4t(uint32_t& r0, uint32_t& r1, uint32_t& r2, uint32_t& r3,
                                       uint32_t a) {
    asm volatile("ldmatrix.sync.aligned.m8n8.x4.trans.shared.b16 {%0,%1,%2,%3}, [%4];"
                 : "=r"(r0), "=r"(r1), "=r"(r2), "=r"(r3) : "r"(a));
}
#define CP16(dst, src) \
    asm volatile("cp.async.cg.shared.global [%0], [%1], 16;" :: "r"(dst), "l"(src) : "memory")
#define CP_COMMIT() asm volatile("cp.async.commit_group;" ::: "memory")
#define CP_WAIT2()  asm volatile("cp.async.wait_group 2;" ::: "memory")
#define CP_WAIT1()  asm volatile("cp.async.wait_group 1;" ::: "memory")
#define CP_WAIT0()  asm volatile("cp.async.wait_group 0;" ::: "memory")

// ---------------- prep: K,V -> fp16 ----------------
__global__ __launch_bounds__(256)
void cvt_kernel(const float* __restrict__ K, const float* __restrict__ V)
{
    size_t i = (size_t)blockIdx.x * 256 + threadIdx.x;   // BH*SEQ*DK/4 = 1M float4
    reinterpret_cast<uint2*>(g_K16)[i] = f4h(reinterpret_cast<const float4*>(K)[i]);
    reinterpret_cast<uint2*>(g_V16)[i] = f4h(reinterpret_cast<const float4*>(V)[i]);
}

// ---------------- main attention ----------------
__global__ __launch_bounds__(256, 2)
void attn_h16_kernel(const float* __restrict__ Q,
                     const int*   __restrict__ mask,
                     float* __restrict__ out,     // may be null
                     float* __restrict__ wout)    // may be null (normalized)
{
    extern __shared__ __align__(16) char smc[];
    float* sadd = reinterpret_cast<float*>(smc + ADDB);
    float* sL   = reinterpret_cast<float*>(smc + LB);
    float* sIL  = reinterpret_cast<float*>(smc + ILB);

    const int tid  = threadIdx.x;
    const int lane = tid & 31;
    const int warp = tid >> 5;
    const int g    = lane >> 2;          // 0..7
    const int tg   = lane & 3;           // 0..3

    const int bh = blockIdx.y;
    const int q0 = blockIdx.x * TQ;
    const int b  = bh >> 4;

    const uint32_t smb = (uint32_t)__cvta_generic_to_shared(smc);
    const uint4* K16g = reinterpret_cast<const uint4*>(g_K16 + (size_t)bh * SEQ * DK);
    const uint4* V16g = reinterpret_cast<const uint4*>(g_V16 + (size_t)bh * SEQ * DK);

    // ---- Q tile (scaled fp16) + mask addend (-16 shift folded) ----
    {
        const float4* Qg = reinterpret_cast<const float4*>(
            Q + ((size_t)bh * SEQ + q0) * DK);
        #pragma unroll
        for (int i = 0; i < 4; ++i) {
            int fi = i * 256 + tid, row = fi >> 4, c4 = fi & 15;
            float4 v = Qg[fi];
            v.x *= 0.125f; v.y *= 0.125f; v.z *= 0.125f; v.w *= 0.125f;
            *reinterpret_cast<uint2*>(smc + QB + row * 144 + c4 * 8) = f4h(v);
        }
        const int* mrow = mask + (size_t)b * SEQ;
        #pragma unroll
        for (int i = 0; i < 8; ++i) {
            int k = i * 256 + tid;
            sadd[k] = mrow[k] ? -16.0f : -1e9f;
        }
    }

    // ---- ldmatrix lane addressing ----
    const int laneRow = (lane & 7) + ((lane >> 3) & 1) * 8;
    const int laneSel = (lane >> 4) & 1;

    // =============== PASS 1: L only. Warp = m64 x n8 (4-deep cp.async K ring) ===============
    {
        // issue K tile t -> ring buffer t&3
        auto issueK = [&](int t) {
            const uint32_t kb = smb + BUF0 + (uint32_t)(t & 3) * 9216;
            #pragma unroll
            for (int i = 0; i < 2; ++i) {
                int fi = i * 256 + tid;
                CP16(kb + (uint32_t)((fi >> 3) * 144 + (fi & 7) * 16),
                     (const void*)(K16g + (size_t)t * 512 + fi));
            }
            CP_COMMIT();
        };
        issueK(0); issueK(1); issueK(2);
        __syncthreads();   // Q + addend visible

        // A-frags for all 4 m16 tiles (warp spans m64)
        uint32_t qa1[4][4][4];
        #pragma unroll
        for (int i = 0; i < 4; ++i) {
            uint32_t a = smb + QB + (uint32_t)((i * 16 + laneRow) * 144 + laneSel * 16);
            #pragma unroll
            for (int kc = 0; kc < 4; ++kc)
                ldsm4(qa1[i][kc][0], qa1[i][kc][1], qa1[i][kc][2], qa1[i][kc][3], a + kc * 32);
        }

        // B-frag address: warp's 8 keys; 4 lane-groups pick (col-half, kc-pair slice)
        const uint32_t p1off = (uint32_t)((warp * 8 + (lane & 7)) * 144
                                          + ((lane >> 3) & 3) * 16);
        float lg[4][2] = {};

        for (int t = 0; t < NT; ++t) {
            if (t <= NT - 3)      CP_WAIT2();
            else if (t == NT - 2) CP_WAIT1();
            else                  CP_WAIT0();
            __syncthreads();

            const uint32_t kb = smb + BUF0 + (uint32_t)(t & 3) * 9216 + p1off;
            float acc[4][4] = {};
            #pragma unroll
            for (int kc2 = 0; kc2 < 2; ++kc2) {
                uint32_t r0, r1, r2, r3;   // (r0,r1)=frag kc=2*kc2, (r2,r3)=kc=2*kc2+1
                ldsm4(r0, r1, r2, r3, kb + kc2 * 64);
                #pragma unroll
                for (int i = 0; i < 4; ++i) {
                    mma16(acc[i], qa1[i][2*kc2][0],   qa1[i][2*kc2][1],
                                  qa1[i][2*kc2][2],   qa1[i][2*kc2][3],   r0, r1);
                    mma16(acc[i], qa1[i][2*kc2+1][0], qa1[i][2*kc2+1][1],
                                  qa1[i][2*kc2+1][2], qa1[i][2*kc2+1][3], r2, r3);
                }
            }
            float2 ad = *reinterpret_cast<const float2*>(sadd + t * TK + warp * 8 + 2 * tg);
            #pragma unroll
            for (int i = 0; i < 4; ++i) {
                lg[i][0] += __expf(acc[i][0] + ad.x) + __expf(acc[i][1] + ad.y);
                lg[i][1] += __expf(acc[i][2] + ad.x) + __expf(acc[i][3] + ad.y);
            }
            __syncthreads();
            if (t + 3 < NT) issueK(t + 3);
        }

        #pragma unroll
        for (int i = 0; i < 4; ++i)
            #pragma unroll
            for (int h = 0; h < 2; ++h) {
                lg[i][h] += __shfl_xor_sync(~0u, lg[i][h], 1);
                lg[i][h] += __shfl_xor_sync(~0u, lg[i][h], 2);
            }
        if (tg == 0) {
            #pragma unroll
            for (int i = 0; i < 4; ++i) {
                sL[warp * TQ + i * 16 + g]     = lg[i][0];
                sL[warp * TQ + i * 16 + g + 8] = lg[i][1];
            }
        }
        __syncthreads();
        if (tid < TQ) {
            float s = 0.f;
            #pragma unroll
            for (int w = 0; w < 8; ++w) s += sL[w * TQ + tid];
            sIL[tid] = 1.0f / s;
        }
        __syncthreads();
    }

    // =============== PASS 2: m16 x n32 (round-15 layout), cp.async K+V ===============
    const int mw = warp >> 1;            // 0..3
    const int nw = warp & 1;             // 0..1
    const uint32_t aBase   = smb + QB + (uint32_t)((mw * 16 + laneRow) * 144 + laneSel * 16);
    const uint32_t bRowOff = (uint32_t)((nw * 32 + laneRow) * 144 + laneSel * 16);

    uint32_t qa[4][4];
    #pragma unroll
    for (int kc = 0; kc < 4; ++kc)
        ldsm4(qa[kc][0], qa[kc][1], qa[kc][2], qa[kc][3], aBase + kc * 32);

    const float inv0 = sIL[mw * 16 + g];
    const float inv8 = sIL[mw * 16 + g + 8];

    float o[8][4] = {};
    {
        // issue tile t: K -> buf(t&1), V -> buf(2+(t&1))
        auto issue2 = [&](int t) {
            const uint32_t kb = smb + BUF0 + (uint32_t)(t & 1) * 9216;
            const uint32_t vb = smb + BUF0 + (uint32_t)(2 + (t & 1)) * 9216;
            #pragma unroll
            for (int i = 0; i < 2; ++i) {
                int fi = i * 256 + tid;
                uint32_t d = (uint32_t)((fi >> 3) * 144 + (fi & 7) * 16);
                CP16(kb + d, (const void*)(K16g + (size_t)t * 512 + fi));
                CP16(vb + d, (const void*)(V16g + (size_t)t * 512 + fi));
            }
            CP_COMMIT();
        };
        issue2(0); issue2(1);

        for (int t = 0; t < NT; ++t) {
            if (t < NT - 1) CP_WAIT1();
            else            CP_WAIT0();
            __syncthreads();   // tile t resident; prior reads of this parity done

            const uint32_t bBase = smb + BUF0 + (uint32_t)(t & 1) * 9216 + bRowOff;
            const uint32_t vBase = smb + BUF0 + (uint32_t)(2 + (t & 1)) * 9216 + bRowOff;

            float acc[4][4] = {};
            #pragma unroll
            for (int kc = 0; kc < 4; ++kc) {
                #pragma unroll
                for (int p = 0; p < 2; ++p) {
                    uint32_t r0, r1, r2, r3;
                    ldsm4(r0, r1, r2, r3, bBase + p * (16 * 144) + kc * 32);
                    mma16(acc[2*p],   qa[kc][0], qa[kc][1], qa[kc][2], qa[kc][3], r0, r2);
                    mma16(acc[2*p+1], qa[kc][0], qa[kc][1], qa[kc][2], qa[kc][3], r1, r3);
                }
            }

            // u = exp(s+ad); write NORMALIZED weights; fp16 P = u*e^16
            #pragma unroll
            for (int nt = 0; nt < 4; ++nt) {
                int colL = nw * 32 + nt * 8 + 2 * tg;
                float2 ad = *reinterpret_cast<const float2*>(sadd + t * TK + colL);
                float u00 = __expf(acc[nt][0] + ad.x);
                float u01 = __expf(acc[nt][1] + ad.y);
                float u10 = __expf(acc[nt][2] + ad.x);
                float u11 = __expf(acc[nt][3] + ad.y);
                if (wout) {
                    size_t base = ((size_t)bh * SEQ + q0 + mw * 16 + g) * SEQ + t * TK + colL;
                    *reinterpret_cast<float2*>(wout + base)           = make_float2(u00 * inv0, u01 * inv0);
                    *reinterpret_cast<float2*>(wout + base + 8 * SEQ) = make_float2(u10 * inv8, u11 * inv8);
                }
                acc[nt][0] = u00; acc[nt][1] = u01;
                acc[nt][2] = u10; acc[nt][3] = u11;
            }
            uint32_t pa[2][4];
            #pragma unroll
            for (int kc = 0; kc < 2; ++kc) {
                pa[kc][0] = pack2(acc[2*kc][0]   * E16F, acc[2*kc][1]   * E16F);
                pa[kc][1] = pack2(acc[2*kc][2]   * E16F, acc[2*kc][3]   * E16F);
                pa[kc][2] = pack2(acc[2*kc+1][0] * E16F, acc[2*kc+1][1] * E16F);
                pa[kc][3] = pack2(acc[2*kc+1][2] * E16F, acc[2*kc+1][3] * E16F);
            }

            #pragma unroll
            for (int kc = 0; kc < 2; ++kc) {
                #pragma unroll
                for (int dp = 0; dp < 4; ++dp) {
                    uint32_t r0, r1, r2, r3;
                    ldsm4t(r0, r1, r2, r3, vBase + kc * (16 * 144) + dp * 32);
                    mma16(o[2*dp],   pa[kc][0], pa[kc][1], pa[kc][2], pa[kc][3], r0, r1);
                    mma16(o[2*dp+1], pa[kc][0], pa[kc][1], pa[kc][2], pa[kc][3], r2, r3);
                }
            }
            __syncthreads();   // all reads of this parity done before refill
            if (t + 2 < NT) issue2(t + 2);
        }
    }

    // ---- combine O across nw pair, normalize by inv*e^-16, write out ----
    __syncthreads();
    float* red = reinterpret_cast<float*>(smc);   // 64*68*4 = 17408 B (Q + buf region)
    if (nw == 1) {
        #pragma unroll
        for (int dn = 0; dn < 8; ++dn) {
            int c = dn * 8 + 2 * tg;
            red[(mw * 16 + g) * 68 + c]         = o[dn][0];
            red[(mw * 16 + g) * 68 + c + 1]     = o[dn][1];
            red[(mw * 16 + g + 8) * 68 + c]     = o[dn][2];
            red[(mw * 16 + g + 8) * 68 + c + 1] = o[dn][3];
        }
    }
    __syncthreads();
    if (nw == 0 && out) {
        float s0 = inv0 * INVE16;
        float s8 = inv8 * INVE16;
        size_t base = ((size_t)bh * SEQ + q0 + mw * 16 + g) * DK;
        #pragma unroll
        for (int dn = 0; dn < 8; ++dn) {
            int c = dn * 8 + 2 * tg;
            float2 lo = make_float2((o[dn][0] + red[(mw * 16 + g) * 68 + c])     * s0,
                                    (o[dn][1] + red[(mw * 16 + g) * 68 + c + 1]) * s0);
            float2 hi = make_float2((o[dn][2] + red[(mw * 16 + g + 8) * 68 + c])     * s8,
                                    (o[dn][3] + red[(mw * 16 + g + 8) * 68 + c + 1]) * s8);
            *reinterpret_cast<float2*>(out + base + c)          = lo;
            *reinterpret_cast<float2*>(out + base + 8 * DK + c) = hi;
        }
    }
}

extern "C" void kernel_launch(void* const* d_in, const int* in_sizes, int n_in,
                              void* d_out, int out_size)
{
    const float* Q    = (const float*)d_in[0];
    const float* K    = (const float*)d_in[1];
    const float* V    = (const float*)d_in[2];
    const int*   mask = (const int*)d_in[3];

    const long long O = (long long)BH * SEQ * DK;    //   4,194,304
    const long long W = (long long)BH * SEQ * SEQ;   // 134,217,728

    float* out_ptr = nullptr;
    float* w_ptr   = nullptr;
    if ((long long)out_size >= O + W) {
        out_ptr = (float*)d_out;
        w_ptr   = (float*)d_out + O;
    } else if ((long long)out_size == W) {
        w_ptr   = (float*)d_out;
    } else {
        out_ptr = (float*)d_out;
    }

    cvt_kernel<<<4096, 256>>>(K, V);

    cudaFuncSetAttribute(attn_h16_kernel,
                         cudaFuncAttributeMaxDynamicSharedMemorySize, SMEM_BYTES);
    dim3 grid(SEQ / TQ, BH);
    attn_h16_kernel<<<grid, 256, SMEM_BYTES>>>(Q, mask, out_ptr, w_ptr);
}